// round 6
// baseline (speedup 1.0000x reference)
#include <cuda_runtime.h>
#include <math.h>

#define BB 16
#define NN 16384
#define TOTAL (BB * NN)
#define NCHUNK (NN / 32)        // 512
#define NGROUP (NCHUNK / 4)     // 128 groups of 4 chunks

// Scratch (padded so tail prefetches stay in-bounds; pad values never used).
__device__ float4 g_cA[TOTAL + 512];
__device__ float4 g_cB[TOTAL + 512];
__device__ int    g_mt[TOTAL + 512];

// ---------------------------------------------------------------------------
// Pass 1: fully parallel coefficient computation.
//   blk[0]=b0*w0; blk[j]=b0*w[j]+a1*w[j-1] (j=1..5); blk[6]=a1*w5;  B.w=x[n].
//   meta = lo | (mm<<8) | (r<<16):
//     lo = (base-6)&255  ring slot of window start (base = n - zc)
//     mm = (n&31) - zc + 97   (tap j is in chunk c-1  <=>  mm >= 65+j)
//     r  = base & 31          shuffle lane for tap 0
// ---------------------------------------------------------------------------
__global__ void __launch_bounds__(256)
coef_kernel(const float* __restrict__ f0,
            const float* __restrict__ x,
            const float* __restrict__ lb)
{
    int i = blockIdx.x * blockDim.x + threadIdx.x;
    if (i >= TOTAL) return;
    int n = i & (NN - 1);

    float2 gp = reinterpret_cast<const float2*>(lb)[i];
    float g  = 0.99f * gp.x;
    float p  = gp.y;
    float b0 = g * (1.0f - p);
    float a1 = g * p;
    float f0c = f0[i] - a1 / (b0 + a1 + 1e-7f);

    int   zc    = (int)floorf(f0c) - 2;     // in [37, 97]
    float alpha = f0c - (float)zc;          // in [2, 3)

    float u0 = alpha;
    float u1 = alpha - 1.0f;
    float u2 = alpha - 2.0f;
    float u3 = alpha - 3.0f;
    float u4 = alpha - 4.0f;
    float u5 = alpha - 5.0f;

    float pre1 = u0;
    float pre2 = pre1 * u1;
    float pre3 = pre2 * u2;
    float pre4 = pre3 * u3;
    float pre5 = pre4 * u4;
    float suf4 = u5;
    float suf3 = suf4 * u4;
    float suf2 = suf3 * u3;
    float suf1 = suf2 * u2;
    float suf0 = suf1 * u1;

    float w0 = suf0        * (-1.0f / 120.0f);
    float w1 = pre1 * suf1 * ( 1.0f /  24.0f);
    float w2 = pre2 * suf2 * (-1.0f /  12.0f);
    float w3 = pre3 * suf3 * ( 1.0f /  12.0f);
    float w4 = pre4 * suf4 * (-1.0f /  24.0f);
    float w5 = pre5        * ( 1.0f / 120.0f);

    g_cA[i] = make_float4(b0 * w0,
                          fmaf(b0, w1, a1 * w0),
                          fmaf(b0, w2, a1 * w1),
                          fmaf(b0, w3, a1 * w2));
    g_cB[i] = make_float4(fmaf(b0, w4, a1 * w3),
                          fmaf(b0, w5, a1 * w4),
                          a1 * w5,
                          x[i]);
    int base = n - zc;
    int lo   = (base - 6) & 255;
    int mm   = (n & 31) - zc + 97;          // in [0, 91]
    int r    = base & 31;
    g_mt[i] = lo | (mm << 8) | (r << 16);
}

// ---------------------------------------------------------------------------
// cp.async helpers
// ---------------------------------------------------------------------------
__device__ __forceinline__ void cp16(void* dst, const void* src) {
    unsigned int d = (unsigned int)__cvta_generic_to_shared(dst);
    asm volatile("cp.async.ca.shared.global [%0], [%1], 16;" :: "r"(d), "l"(src));
}
__device__ __forceinline__ void cp4(void* dst, const void* src) {
    unsigned int d = (unsigned int)__cvta_generic_to_shared(dst);
    asm volatile("cp.async.ca.shared.global [%0], [%1], 4;" :: "r"(d), "l"(src));
}
__device__ __forceinline__ void cp_commit() {
    asm volatile("cp.async.commit_group;");
}
__device__ __forceinline__ void cp_wait2() {
    asm volatile("cp.async.wait_group 2;");
}

// ---------------------------------------------------------------------------
// Pass 2: sequential recurrence, one warp per batch row.
//   y[n] = x[n] + sum_{j=0..6} blk[j]*y[base-j],  delays in [37, 103].
//   Chunks processed in pairs (even, odd) with ONE __syncwarp per pair:
//     - pair-start sync publishes ring STS through chunk even-1
//     - even chunk: all 7 taps from the ring (as round 5)
//     - odd  chunk: taps from chunk c-1 via __shfl_sync of the even chunk's
//       acc register (no memory ordering needed); taps from chunks <= c-2
//       from the ring. Per-tap choice is the destination-side predicate
//       mm >= 65+j. Stale ring reads under selected-out taps are discarded.
//   Ring: 256 + 7-slot mirror; pre-zeroed => zero initial state for free.
//   Coefficients stream through a 16-stage SMEM cp.async pipeline (~8-chunk
//   lead, wait_group 2).
// ---------------------------------------------------------------------------
struct SmemCoef {
    float4 A[16][32];
    float4 B[16][32];
    int    I[16][32];
};

__device__ __forceinline__ void prefetch_chunk(SmemCoef* s, int st, int c, int lane,
                                               const float4* cA, const float4* cB,
                                               const int* cI)
{
    int idx = c * 32 + lane;
    cp16(&s->A[st][lane], cA + idx);
    cp16(&s->B[st][lane], cB + idx);
    cp4 (&s->I[st][lane], cI + idx);
}

template<bool MIRROR>
__device__ __forceinline__ float proc_even(SmemCoef* s, int st, int wslot,
                                           int lane, bool lane_lt7,
                                           float* ring, float* op)
{
    const float4 A   = s->A[st][lane];
    const float4 B   = s->B[st][lane];
    const int    lo  = s->I[st][lane] & 255;

    const float* w = ring + lo;              // window [lo, lo+6], never wraps
    float v6 = w[0];
    float v5 = w[1];
    float v4 = w[2];
    float v3 = w[3];
    float v2 = w[4];
    float v1 = w[5];
    float v0 = w[6];

    float t0 = fmaf(A.x, v0, B.w);           // x[n] + blk0*v0
    float t1 = fmaf(A.z, v2, A.y * v1);
    float t2 = fmaf(B.x, v4, A.w * v3);
    float t3 = fmaf(B.z, v6, B.y * v5);
    float acc = (t0 + t1) + (t2 + t3);

    ring[wslot + lane] = acc;
    if (MIRROR && lane_lt7) ring[256 + lane] = acc;
    *op = acc;
    return acc;
}

__device__ __forceinline__ float proc_odd(SmemCoef* s, int st, int wslot,
                                          int lane, float prev,
                                          float* ring, float* op)
{
    const float4 A    = s->A[st][lane];
    const float4 B    = s->B[st][lane];
    const int    meta = s->I[st][lane];
    const int    lo   = meta & 255;
    const int    mm   = (meta >> 8) & 255;
    const int    r    = meta >> 16;

    const float* w = ring + lo;              // stale where shfl wins; discarded
    float g6 = w[0];
    float g5 = w[1];
    float g4 = w[2];
    float g3 = w[3];
    float g2 = w[4];
    float g1 = w[5];
    float g0 = w[6];

    float h0 = __shfl_sync(0xffffffffu, prev,  r          );
    float h1 = __shfl_sync(0xffffffffu, prev, (r - 1) & 31);
    float h2 = __shfl_sync(0xffffffffu, prev, (r - 2) & 31);
    float h3 = __shfl_sync(0xffffffffu, prev, (r - 3) & 31);
    float h4 = __shfl_sync(0xffffffffu, prev, (r - 4) & 31);
    float h5 = __shfl_sync(0xffffffffu, prev, (r - 5) & 31);
    float h6 = __shfl_sync(0xffffffffu, prev, (r - 6) & 31);

    float v0 = (mm >= 65) ? h0 : g0;
    float v1 = (mm >= 66) ? h1 : g1;
    float v2 = (mm >= 67) ? h2 : g2;
    float v3 = (mm >= 68) ? h3 : g3;
    float v4 = (mm >= 69) ? h4 : g4;
    float v5 = (mm >= 70) ? h5 : g5;
    float v6 = (mm >= 71) ? h6 : g6;

    float t0 = fmaf(A.x, v0, B.w);
    float t1 = fmaf(A.z, v2, A.y * v1);
    float t2 = fmaf(B.x, v4, A.w * v3);
    float t3 = fmaf(B.z, v6, B.y * v5);
    float acc = (t0 + t1) + (t2 + t3);

    ring[wslot + lane] = acc;
    *op = acc;
    return acc;
}

// One phase = consume 4 chunks (2 pairs) and prefetch group grp+3.
template<int STB, int WB, bool MIR, int NSTB>
__device__ __forceinline__ void phase(SmemCoef* s, int grp, int lane, bool lane_lt7,
                                      float* ring, float* op,
                                      const float4* cA, const float4* cB, const int* cI)
{
    cp_wait2();                               // group grp's data is resident
    const int pc0 = (grp + 3) * 4;            // chunks to prefetch
    float* opg = op + grp * 128;

    __syncwarp();                             // publish STS through chunk 4g-1
    float a0 = proc_even<MIR>(s, STB + 0, WB, lane, lane_lt7, ring, opg);
    float a1 = proc_odd      (s, STB + 1, WB + 32, lane, a0, ring, opg + 32);
    (void)a1;
    prefetch_chunk(s, NSTB + 0, pc0 + 0, lane, cA, cB, cI);
    prefetch_chunk(s, NSTB + 1, pc0 + 1, lane, cA, cB, cI);

    __syncwarp();                             // publish STS through chunk 4g+1
    float a2 = proc_even<false>(s, STB + 2, WB + 64, lane, lane_lt7, ring, opg + 64);
    proc_odd(s, STB + 3, WB + 96, lane, a2, ring, opg + 96);
    prefetch_chunk(s, NSTB + 2, pc0 + 2, lane, cA, cB, cI);
    prefetch_chunk(s, NSTB + 3, pc0 + 3, lane, cA, cB, cI);
    cp_commit();
}

__global__ void __launch_bounds__(32, 1)
lpc_kernel(float* __restrict__ out)
{
    __shared__ SmemCoef sc;
    __shared__ float ring[264];

    const int b    = blockIdx.x;
    const int lane = threadIdx.x;
    const bool lane_lt7 = lane < 7;
    const float4* __restrict__ cA = g_cA + b * NN;
    const float4* __restrict__ cB = g_cB + b * NN;
    const int*    __restrict__ cI = g_mt + b * NN;
    float* __restrict__ op = out + b * NN + lane;

#pragma unroll
    for (int k = 0; k < 8; k++) ring[lane + 32 * k] = 0.0f;
    if (lane < 8) ring[256 + lane] = 0.0f;

    // prime pipeline: groups 0,1,2 -> stages 0-11
#pragma unroll
    for (int gp = 0; gp < 3; gp++) {
#pragma unroll
        for (int k = 0; k < 4; k++)
            prefetch_chunk(&sc, gp * 4 + k, gp * 4 + k, lane, cA, cB, cI);
        cp_commit();
    }

    for (int g = 0; g < NGROUP; g += 4) {
        // chunk c writes ring slot (c&7)*32; groups alternate base 0/128;
        // mirror store needed only on chunks c % 8 == 0 (k==0 of MIR phases)
        phase< 0,   0, true,  12>(&sc, g + 0, lane, lane_lt7, ring, op, cA, cB, cI);
        phase< 4, 128, false,  0>(&sc, g + 1, lane, lane_lt7, ring, op, cA, cB, cI);
        phase< 8,   0, true,   4>(&sc, g + 2, lane, lane_lt7, ring, op, cA, cB, cI);
        phase<12, 128, false,  8>(&sc, g + 3, lane, lane_lt7, ring, op, cA, cB, cI);
    }
}

// ---------------------------------------------------------------------------
// Inputs (metadata order): f0 [B,N] f32, x [B,N] f32, l_b [B,N,2] f32, K int32
// Output: y [B,N] f32
// ---------------------------------------------------------------------------
extern "C" void kernel_launch(void* const* d_in, const int* in_sizes, int n_in,
                              void* d_out, int out_size)
{
    const float* f0 = (const float*)d_in[0];
    const float* x  = (const float*)d_in[1];
    const float* lb = (const float*)d_in[2];
    float* out = (float*)d_out;

    coef_kernel<<<TOTAL / 256, 256>>>(f0, x, lb);
    lpc_kernel<<<BB, 32>>>(out);
}

// round 7
// speedup vs baseline: 1.2573x; 1.2573x over previous
#include <cuda_runtime.h>
#include <math.h>

#define BB 16
#define NN 16384
#define TOTAL (BB * NN)
#define NCHUNK (NN / 32)        // 512
#define NGROUP (NCHUNK / 4)     // 128 groups of 4 chunks

// Scratch (padded so tail prefetches stay in-bounds; pad values never used).
__device__ float4 g_cA[TOTAL + 512];
__device__ float4 g_cB[TOTAL + 512];
__device__ int    g_lo[TOTAL + 512];

// ---------------------------------------------------------------------------
// Pass 1: fully parallel coefficient computation.
//   blk[0]=b0*w0; blk[j]=b0*w[j]+a1*w[j-1] (j=1..5); blk[6]=a1*w5;  B.w=x[n].
//   Stores lo = (n - zc - 6) & 255 (ring slot of the 7-tap window start).
// ---------------------------------------------------------------------------
__global__ void __launch_bounds__(256)
coef_kernel(const float* __restrict__ f0,
            const float* __restrict__ x,
            const float* __restrict__ lb)
{
    int i = blockIdx.x * blockDim.x + threadIdx.x;
    if (i >= TOTAL) return;
    int n = i & (NN - 1);

    float2 gp = reinterpret_cast<const float2*>(lb)[i];
    float g  = 0.99f * gp.x;
    float p  = gp.y;
    float b0 = g * (1.0f - p);
    float a1 = g * p;
    float f0c = f0[i] - a1 / (b0 + a1 + 1e-7f);

    int   zc    = (int)floorf(f0c) - 2;     // in [37, 97]
    float alpha = f0c - (float)zc;          // in [2, 3)

    float u0 = alpha;
    float u1 = alpha - 1.0f;
    float u2 = alpha - 2.0f;
    float u3 = alpha - 3.0f;
    float u4 = alpha - 4.0f;
    float u5 = alpha - 5.0f;

    float pre1 = u0;
    float pre2 = pre1 * u1;
    float pre3 = pre2 * u2;
    float pre4 = pre3 * u3;
    float pre5 = pre4 * u4;
    float suf4 = u5;
    float suf3 = suf4 * u4;
    float suf2 = suf3 * u3;
    float suf1 = suf2 * u2;
    float suf0 = suf1 * u1;

    float w0 = suf0        * (-1.0f / 120.0f);
    float w1 = pre1 * suf1 * ( 1.0f /  24.0f);
    float w2 = pre2 * suf2 * (-1.0f /  12.0f);
    float w3 = pre3 * suf3 * ( 1.0f /  12.0f);
    float w4 = pre4 * suf4 * (-1.0f /  24.0f);
    float w5 = pre5        * ( 1.0f / 120.0f);

    g_cA[i] = make_float4(b0 * w0,
                          fmaf(b0, w1, a1 * w0),
                          fmaf(b0, w2, a1 * w1),
                          fmaf(b0, w3, a1 * w2));
    g_cB[i] = make_float4(fmaf(b0, w4, a1 * w3),
                          fmaf(b0, w5, a1 * w4),
                          a1 * w5,
                          x[i]);
    g_lo[i] = (n - zc - 6) & 255;
}

// ---------------------------------------------------------------------------
// cp.async helpers
// ---------------------------------------------------------------------------
__device__ __forceinline__ void cp16(void* dst, const void* src) {
    unsigned int d = (unsigned int)__cvta_generic_to_shared(dst);
    asm volatile("cp.async.ca.shared.global [%0], [%1], 16;" :: "r"(d), "l"(src));
}
__device__ __forceinline__ void cp4(void* dst, const void* src) {
    unsigned int d = (unsigned int)__cvta_generic_to_shared(dst);
    asm volatile("cp.async.ca.shared.global [%0], [%1], 4;" :: "r"(d), "l"(src));
}
__device__ __forceinline__ void cp_commit() {
    asm volatile("cp.async.commit_group;");
}
__device__ __forceinline__ void cp_wait2() {
    asm volatile("cp.async.wait_group 2;");
}
// Named-barrier self-sync: one warp, count 32 -> releases immediately at the
// BAR floor and drains this warp's pending STS (orders STS(c) before LDS(c+1)).
__device__ __forceinline__ void bar15() {
    asm volatile("bar.sync 15, 32;" ::: "memory");
}

// ---------------------------------------------------------------------------
// Pass 2: sequential recurrence. One block = 2 warps per batch row.
//   warp 0 (compute): y[n] = x[n] + sum_j blk[j]*y[n-zc-j], delays in [37,103].
//     - SMEM ring (256 + 7-slot mirror): branchless 7-tap window, immediate
//       offsets; bar.sync 15,32 per chunk orders STS->LDS (cheaper than
//       WARPSYNC); pre-zeroed ring gives the zero initial state for free.
//     - the group's 12 coefficient LDS are batched into registers right after
//       the group barrier, so only ring LDS sit on the per-chunk chain.
//   warp 1 (helper): streams coefficients gmem->SMEM via cp.async, 16-stage
//     buffer, 3-group lead, one __syncthreads per 4-chunk group publishes
//     the next group to the compute warp.
// ---------------------------------------------------------------------------
struct SmemCoef {
    float4 A[16][32];
    float4 B[16][32];
    int    I[16][32];
};

__device__ __forceinline__ void prefetch_chunk(SmemCoef* s, int st, int c, int lane,
                                               const float4* cA, const float4* cB,
                                               const int* cI)
{
    int idx = c * 32 + lane;
    cp16(&s->A[st][lane], cA + idx);
    cp16(&s->B[st][lane], cB + idx);
    cp4 (&s->I[st][lane], cI + idx);
}

__global__ void __launch_bounds__(64, 1)
lpc_kernel(float* __restrict__ out)
{
    __shared__ SmemCoef sc;
    __shared__ float ring[264];

    const int b    = blockIdx.x;
    const int tid  = threadIdx.x;
    const int wid  = tid >> 5;
    const int lane = tid & 31;
    const float4* __restrict__ cA = g_cA + b * NN;
    const float4* __restrict__ cB = g_cB + b * NN;
    const int*    __restrict__ cI = g_lo + b * NN;

    if (wid == 0) {
        // zero the ring (implements zero initial state via wrap mapping)
#pragma unroll
        for (int k = 0; k < 8; k++) ring[lane + 32 * k] = 0.0f;
        if (lane < 8) ring[256 + lane] = 0.0f;
    } else {
        // prime pipeline: groups 0,1,2 -> stages 0-11
#pragma unroll
        for (int gp = 0; gp < 3; gp++) {
#pragma unroll
            for (int k = 0; k < 4; k++)
                prefetch_chunk(&sc, gp * 4 + k, gp * 4 + k, lane, cA, cB, cI);
            cp_commit();
        }
        cp_wait2();                     // group 0 resident
    }
    __syncthreads();

    if (wid == 0) {
        // ---------------- compute warp ----------------
        const bool lane_lt7 = lane < 7;
        float* __restrict__ op = out + b * NN + lane;

        for (int g = 0; g < NGROUP; g++) {
            const int st = (g & 3) * 4;
            const int wb = (g & 1) * 128;         // ring write base for group
            const bool mir = (g & 1) == 0;        // chunk c%8==0 is k==0 here

            // batch the group's coefficients into registers (12 LDS, latency
            // overlapped here instead of re-arming after each bar15)
            float4 A0 = sc.A[st + 0][lane], B0 = sc.B[st + 0][lane];
            float4 A1 = sc.A[st + 1][lane], B1 = sc.B[st + 1][lane];
            float4 A2 = sc.A[st + 2][lane], B2 = sc.B[st + 2][lane];
            float4 A3 = sc.A[st + 3][lane], B3 = sc.B[st + 3][lane];
            int l0 = sc.I[st + 0][lane];
            int l1 = sc.I[st + 1][lane];
            int l2 = sc.I[st + 2][lane];
            int l3 = sc.I[st + 3][lane];

            float* opg = op + g * 128;

#pragma unroll
            for (int k = 0; k < 4; k++) {
                if (k > 0) bar15();               // k==0 ordered by __syncthreads
                const float4 A = (k == 0) ? A0 : (k == 1) ? A1 : (k == 2) ? A2 : A3;
                const float4 B = (k == 0) ? B0 : (k == 1) ? B1 : (k == 2) ? B2 : B3;
                const int   lo = (k == 0) ? l0 : (k == 1) ? l1 : (k == 2) ? l2 : l3;

                const float* w = ring + lo;       // [lo, lo+6], never wraps
                float v6 = w[0];
                float v5 = w[1];
                float v4 = w[2];
                float v3 = w[3];
                float v2 = w[4];
                float v1 = w[5];
                float v0 = w[6];

                float t0 = fmaf(A.x, v0, B.w);    // x[n] + blk0*v0
                float t1 = fmaf(A.z, v2, A.y * v1);
                float t2 = fmaf(B.x, v4, A.w * v3);
                float t3 = fmaf(B.z, v6, B.y * v5);
                float acc = (t0 + t1) + (t2 + t3);

                ring[wb + k * 32 + lane] = acc;
                if (mir && k == 0 && lane_lt7) ring[256 + lane] = acc;
                opg[k * 32] = acc;
            }
            __syncthreads();                      // next group published
        }
    } else {
        // ---------------- helper warp ----------------
        for (int g = 0; g < NGROUP; g++) {
            const int pg = g + 3;                 // group to prefetch
            const int st = (pg & 3) * 4;
#pragma unroll
            for (int k = 0; k < 4; k++)
                prefetch_chunk(&sc, st + k, pg * 4 + k, lane, cA, cB, cI);
            cp_commit();
            cp_wait2();                           // group g+1 resident
            __syncthreads();
        }
    }
}

// ---------------------------------------------------------------------------
// Inputs (metadata order): f0 [B,N] f32, x [B,N] f32, l_b [B,N,2] f32, K int32
// Output: y [B,N] f32
// ---------------------------------------------------------------------------
extern "C" void kernel_launch(void* const* d_in, const int* in_sizes, int n_in,
                              void* d_out, int out_size)
{
    const float* f0 = (const float*)d_in[0];
    const float* x  = (const float*)d_in[1];
    const float* lb = (const float*)d_in[2];
    float* out = (float*)d_out;

    coef_kernel<<<TOTAL / 256, 256>>>(f0, x, lb);
    lpc_kernel<<<BB, 64>>>(out);
}